// round 6
// baseline (speedup 1.0000x reference)
#include <cuda_runtime.h>
#include <cstdint>

// out[b, p*20+x, q*20+y] = (x!=y && p!=q) ? P[x,p]+Q[x,q]+Q[y,p]+P[y,q] : 0
//                          + (p==q && x==y) ? Mn[x,p] : 0
// P = F1 @ relu(L1) @ F2^T, Q = F1 @ relu(L2) @ F2^T, Mn = U1 @ U2^T (per batch)
//
// compute_kernel: grid (256), 128 threads. Thread owns e and e+128 of BOTH
//   L1 and L2 (4 columns) -> one A-row broadcast feeds 40 FFMA2; phases
//   1/3/5/6 run once per batch. Full P,Q,Mn to scratch.
// write_kernel: grid (2 p-halves, 256), 512 threads. Per-thread geometry and
//   q-dependent loads hoisted out of the 10-iteration p loop; stage once.

#define NB 256
#define NN 20
#define DD 256
#define STRD 260        // smem row stride for [20][256] tiles

typedef unsigned long long ull;

__device__ float g_scratch[NB * 1200];   // per batch: P[400] | Q[400] | Mn[400]

#define FMA2(acc, x, y) \
    asm("fma.rn.f32x2 %0, %1, %2, %0;" : "+l"(acc) : "l"(x), "l"(y))

__device__ __forceinline__ float2 up64(ull v) {
    float2 r;
    asm("mov.b64 {%0,%1}, %2;" : "=f"(r.x), "=f"(r.y) : "l"(v));
    return r;
}
__device__ __forceinline__ ull dup(float w) {
    ull r;
    asm("mov.b64 %0, {%1,%1};" : "=l"(r) : "f"(w));
    return r;
}

// smem (floats): sA[5120] | sT1[5200] | sT2[5200] | sF[5200]
#define OFF_A  0
#define OFF_T1 5120
#define OFF_T2 10320
#define OFF_F  15520
#define SMEM_FLOATS 20720
#define SMEM_BYTES  (SMEM_FLOATS * 4)

// ---------------------------------------------------------------- compute ---
__device__ __forceinline__ void fma_group(
    ull a10[10], ull a11[10], ull a20[10], ull a21[10],
    const float* sA, int d, float w10, float w11, float w20, float w21)
{
    ull x10 = dup(fmaxf(w10, 0.f));
    ull x11 = dup(fmaxf(w11, 0.f));
    ull x20 = dup(fmaxf(w20, 0.f));
    ull x21 = dup(fmaxf(w21, 0.f));
    const ulonglong2* row = reinterpret_cast<const ulonglong2*>(sA + d * NN);
    #pragma unroll
    for (int v = 0; v < 5; v++) {
        ulonglong2 fp = row[v];
        FMA2(a10[2 * v], fp.x, x10); FMA2(a10[2 * v + 1], fp.y, x10);
        FMA2(a11[2 * v], fp.x, x11); FMA2(a11[2 * v + 1], fp.y, x11);
        FMA2(a20[2 * v], fp.x, x20); FMA2(a20[2 * v + 1], fp.y, x20);
        FMA2(a21[2 * v], fp.x, x21); FMA2(a21[2 * v + 1], fp.y, x21);
    }
}

__global__ void __launch_bounds__(128)
compute_kernel(const float* __restrict__ F1, const float* __restrict__ F2,
               const float* __restrict__ U1, const float* __restrict__ U2,
               const float* __restrict__ L1, const float* __restrict__ L2)
{
    extern __shared__ float sm[];
    float* sA  = sm + OFF_A;    // F1^T [d][20]
    float* sT1 = sm + OFF_T1;   // T1 [i][STRD] ; later U1 [i][STRD]
    float* sT2 = sm + OFF_T2;   // T2 [i][STRD] ; later U2 [k][STRD]
    float* sF  = sm + OFF_F;    // F2 [k][STRD]

    const int b = blockIdx.x;
    const int t = threadIdx.x;  // 0..127

    // 1. F1 transposed: sA[d*20+i] = F1[b,i,d]
    {
        const float* f1 = F1 + (size_t)b * NN * DD;
        #pragma unroll
        for (int idx = t; idx < NN * DD; idx += 128) {
            int i = idx >> 8, d = idx & 255;
            sA[d * NN + i] = f1[idx];
        }
    }
    // 3. (early, overlaps) F2 row-major into sF
    {
        const float4* f2v = reinterpret_cast<const float4*>(F2 + (size_t)b * NN * DD);
        #pragma unroll
        for (int i4 = t; i4 < NN * DD / 4; i4 += 128) {
            int k = i4 >> 6, d4 = i4 & 63;
            *reinterpret_cast<float4*>(sF + k * STRD + d4 * 4) = f2v[i4];
        }
    }
    __syncthreads();

    // 2. T1[i,e], T2[i,e] for e in {t, t+128}; one A broadcast -> 40 FMA2.
    {
        const float* l1a = L1 + t;         // col e0 = t
        const float* l1b = L1 + t + 128;   // col e1 = t+128
        const float* l2a = L2 + t;
        const float* l2b = L2 + t + 128;
        ull a10[10], a11[10], a20[10], a21[10];
        #pragma unroll
        for (int j = 0; j < 10; j++) {
            a10[j] = 0ull; a11[j] = 0ull; a20[j] = 0ull; a21[j] = 0ull;
        }

        float wA[4], wB[4];   // [w1e0, w1e1, w2e0, w2e1] for two d's in flight
        wA[0] = l1a[0];  wA[1] = l1b[0];  wA[2] = l2a[0];  wA[3] = l2b[0];
        wB[0] = l1a[DD]; wB[1] = l1b[DD]; wB[2] = l2a[DD]; wB[3] = l2b[DD];

        #pragma unroll 2
        for (int d = 0; d < DD; d += 2) {
            float c0 = wA[0], c1 = wA[1], c2 = wA[2], c3 = wA[3];
            if (d + 2 < DD) {
                wA[0] = l1a[(d + 2) * DD]; wA[1] = l1b[(d + 2) * DD];
                wA[2] = l2a[(d + 2) * DD]; wA[3] = l2b[(d + 2) * DD];
            }
            fma_group(a10, a11, a20, a21, sA, d, c0, c1, c2, c3);

            float e0w = wB[0], e1w = wB[1], e2w = wB[2], e3w = wB[3];
            if (d + 3 < DD) {
                wB[0] = l1a[(d + 3) * DD]; wB[1] = l1b[(d + 3) * DD];
                wB[2] = l2a[(d + 3) * DD]; wB[3] = l2b[(d + 3) * DD];
            }
            fma_group(a10, a11, a20, a21, sA, d + 1, e0w, e1w, e2w, e3w);
        }

        // store T row-major: sT[i*STRD + e]
        #pragma unroll
        for (int v = 0; v < 10; v++) {
            float2 f;
            f = up64(a10[v]);
            sT1[(2 * v) * STRD + t]             = f.x;
            sT1[(2 * v + 1) * STRD + t]         = f.y;
            f = up64(a11[v]);
            sT1[(2 * v) * STRD + t + 128]       = f.x;
            sT1[(2 * v + 1) * STRD + t + 128]   = f.y;
            f = up64(a20[v]);
            sT2[(2 * v) * STRD + t]             = f.x;
            sT2[(2 * v + 1) * STRD + t]         = f.y;
            f = up64(a21[v]);
            sT2[(2 * v) * STRD + t + 128]       = f.x;
            sT2[(2 * v + 1) * STRD + t + 128]   = f.y;
        }
    }
    __syncthreads();

    // 4. P[i,k], Q[i,k] = T1[i].F2[k], T2[i].F2[k]
    {
        float* dst = g_scratch + b * 1200;
        #pragma unroll 1
        for (int idx = t; idx < NN * NN; idx += 128) {
            int i = idx / NN, k = idx - i * NN;
            const ulonglong2* Ti1 = reinterpret_cast<const ulonglong2*>(sT1 + i * STRD);
            const ulonglong2* Ti2 = reinterpret_cast<const ulonglong2*>(sT2 + i * STRD);
            const ulonglong2* Fk  = reinterpret_cast<const ulonglong2*>(sF  + k * STRD);
            ull p0 = 0, p1 = 0, q0 = 0, q1 = 0;
            #pragma unroll
            for (int v = 0; v < DD / 4; v++) {
                ulonglong2 fv = Fk[v];
                ulonglong2 t1 = Ti1[v];
                ulonglong2 t2 = Ti2[v];
                FMA2(p0, t1.x, fv.x);
                FMA2(p1, t1.y, fv.y);
                FMA2(q0, t2.x, fv.x);
                FMA2(q1, t2.y, fv.y);
            }
            float2 s0 = up64(p0), s1 = up64(p1);
            dst[idx] = (s0.x + s0.y) + (s1.x + s1.y);
            float2 s2 = up64(q0), s3 = up64(q1);
            dst[400 + idx] = (s2.x + s2.y) + (s3.x + s3.y);
        }
    }
    __syncthreads();

    // 5. U1 -> sT1, U2 -> sT2, row-major
    {
        const float4* u1v = reinterpret_cast<const float4*>(U1 + (size_t)b * NN * DD);
        const float4* u2v = reinterpret_cast<const float4*>(U2 + (size_t)b * NN * DD);
        #pragma unroll
        for (int i4 = t; i4 < NN * DD / 4; i4 += 128) {
            int k = i4 >> 6, d4 = i4 & 63;
            *reinterpret_cast<float4*>(sT1 + k * STRD + d4 * 4) = u1v[i4];
            *reinterpret_cast<float4*>(sT2 + k * STRD + d4 * 4) = u2v[i4];
        }
    }
    __syncthreads();

    // 6. Mn[i,k] = U1[i].U2[k]
    {
        float* dstM = g_scratch + b * 1200 + 800;
        #pragma unroll 1
        for (int idx = t; idx < NN * NN; idx += 128) {
            int i = idx / NN, k = idx - i * NN;
            const ulonglong2* Ui = reinterpret_cast<const ulonglong2*>(sT1 + i * STRD);
            const ulonglong2* Uk = reinterpret_cast<const ulonglong2*>(sT2 + k * STRD);
            ull m0 = 0, m1 = 0;
            #pragma unroll
            for (int v = 0; v < DD / 4; v++) {
                ulonglong2 uv = Ui[v];
                ulonglong2 kv = Uk[v];
                FMA2(m0, uv.x, kv.x);
                FMA2(m1, uv.y, kv.y);
            }
            float2 s0 = up64(m0), s1 = up64(m1);
            dstM[idx] = (s0.x + s0.y) + (s1.x + s1.y);
        }
    }
}

// ------------------------------------------------------------------ write ---
__global__ void __launch_bounds__(512)
write_kernel(float* __restrict__ out)
{
    __shared__ __align__(16) float sPT[NN * 24];   // P^T: [q][y]
    __shared__ __align__(16) float sQT[NN * 24];   // Q^T: [p][y]
    __shared__ float sPd[NN * 21];                 // P: [x][p]
    __shared__ float sQd[NN * 21];                 // Q: [x][q]
    __shared__ float sMnD[NN * 21];                // Mn: [x][p]

    const int h = blockIdx.x;       // p-half: p in [h*10, h*10+10)
    const int b = blockIdx.y;
    const int t = threadIdx.x;

    const float* s = g_scratch + (size_t)b * 1200;

    if (t < 400) {
        int i = t / NN, k = t - i * NN;
        float pv = s[t], qv = s[400 + t], mv = s[800 + t];
        sPd[i * 21 + k] = pv;
        sPT[k * 24 + i] = pv;
        sQd[i * 21 + k] = qv;
        sQT[k * 24 + i] = qv;
        sMnD[i * 21 + k] = mv;
    }
    __syncthreads();

    if (t < 500) {
        const int x0 = t / 100;
        const int cm = t - x0 * 100;          // float4 index within row
        const int q  = cm / 5;
        const int y0 = (cm - q * 5) * 4;

        // hoisted per-thread invariants (no p dependence)
        const float4 pt = *reinterpret_cast<const float4*>(sPT + q * 24 + y0);
        int   xs[4];
        float c2[4];
        int   dxv[4];
        #pragma unroll
        for (int j = 0; j < 4; j++) {
            xs[j]  = x0 + 5 * j;
            c2[j]  = sQd[xs[j] * 21 + q];
            dxv[j] = xs[j] - y0;
        }

        float4* ob = reinterpret_cast<float4*>(out) + (size_t)b * 40000 + cm;

        #pragma unroll 2
        for (int pp = 0; pp < 10; pp++) {
            const int p = h * 10 + pp;
            const float4 qc = *reinterpret_cast<const float4*>(sQT + p * 24 + y0);
            const float bx = pt.x + qc.x, by = pt.y + qc.y;
            const float bz = pt.z + qc.z, bw = pt.w + qc.w;
            float4* obp = ob + p * 2000;

            if (q != p) {
                #pragma unroll
                for (int j = 0; j < 4; j++) {
                    const int x = xs[j];
                    const float c1 = sPd[x * 21 + p] + c2[j];
                    float4 v = make_float4(c1 + bx, c1 + by, c1 + bz, c1 + bw);
                    const int dx = dxv[j];
                    if (dx == 0) v.x = 0.f;
                    else if (dx == 1) v.y = 0.f;
                    else if (dx == 2) v.z = 0.f;
                    else if (dx == 3) v.w = 0.f;
                    __stcs(&obp[x * 100], v);
                }
            } else {
                #pragma unroll
                for (int j = 0; j < 4; j++) {
                    const int x = xs[j];
                    float4 v = make_float4(0.f, 0.f, 0.f, 0.f);
                    const float mn = sMnD[x * 21 + p];
                    const int dx = dxv[j];
                    if (dx == 0) v.x = mn;
                    else if (dx == 1) v.y = mn;
                    else if (dx == 2) v.z = mn;
                    else if (dx == 3) v.w = mn;
                    __stcs(&obp[x * 100], v);
                }
            }
        }
    }
}

// ----------------------------------------------------------------- launch ---
extern "C" void kernel_launch(void* const* d_in, const int* in_sizes, int n_in,
                              void* d_out, int out_size)
{
    // Inputs: F1,F2,U1,U2,G1,G2,H1,H2,mask,lambda1,lambda2 — pick by size.
    const float* Fs[4] = {nullptr, nullptr, nullptr, nullptr};
    const float* Ls[2] = {nullptr, nullptr};
    int nf = 0, nl = 0;
    for (int i = 0; i < n_in; i++) {
        if (in_sizes[i] == NB * NN * DD) {
            if (nf < 4) Fs[nf++] = (const float*)d_in[i];
        } else if (in_sizes[i] == DD * DD) {
            if (nl < 2) Ls[nl++] = (const float*)d_in[i];
        }
    }

    cudaFuncSetAttribute(compute_kernel,
                         cudaFuncAttributeMaxDynamicSharedMemorySize, SMEM_BYTES);

    compute_kernel<<<NB, 128, SMEM_BYTES>>>(Fs[0], Fs[1], Fs[2], Fs[3],
                                            Ls[0], Ls[1]);
    write_kernel<<<dim3(2, NB), 512>>>((float*)d_out);
    (void)out_size;
}